// round 1
// baseline (speedup 1.0000x reference)
#include <cuda_runtime.h>

#define TT   2048
#define BB   2048
#define HH   32
#define DF   8
#define DS   24
#define WPB  4              // warps per block
#define NTHR (WPB * 32)
#define NBLK 128            // 128 blocks * 4 warps * 4 batch = 2048 batch

typedef unsigned long long u64;

__device__ __forceinline__ u64 dup2(float w) {
    u64 d; asm("mov.b64 %0, {%1, %1};" : "=l"(d) : "f"(w)); return d;
}
__device__ __forceinline__ void unpack2(u64 v, float &a, float &b) {
    asm("mov.b64 {%0, %1}, %2;" : "=f"(a), "=f"(b) : "l"(v));
}
__device__ __forceinline__ void fma2(u64 &acc, u64 a, u64 b) {
    asm("fma.rn.f32x2 %0, %1, %2, %0;" : "+l"(acc) : "l"(a), "l"(b));
}
__device__ __forceinline__ float tanh_fast(float x) {
    // tanh(x) = 1 - 2/(e^{2x}+1); MUFU.EX2 + MUFU.RCP based, abs err ~1e-6
    float e = __expf(2.0f * x);
    return 1.0f - __fdividef(2.0f, e + 1.0f);
}

struct SW {
    float4 hf[32], hp[32], hs0[32], hs1[32], hs2[32];   // 4-batch packed state
    float4 xf[2][8], xp[2][8], xs[2][32];               // ping-pong staged inputs
};

__global__ void __launch_bounds__(NTHR, 1) chive_kernel(
    const float* __restrict__ frnn, const float* __restrict__ phrnn, const float* __restrict__ syl,
    const float* __restrict__ Wxf, const float* __restrict__ Whf, const float* __restrict__ bfv,
    const float* __restrict__ Wxp, const float* __restrict__ Whp, const float* __restrict__ bpv,
    const float* __restrict__ Wxs, const float* __restrict__ Whs, const float* __restrict__ bsv,
    const int* __restrict__ fclk, const int* __restrict__ pclk, const int* __restrict__ sfreq,
    float* __restrict__ out)
{
    __shared__ SW sw[WPB];
    __shared__ unsigned char flags[TT];

    const int tid  = threadIdx.x;
    const int w    = tid >> 5;
    const int lane = tid & 31;
    const int j    = lane;

    // ---- precompute warp-uniform update masks (depend only on t) ----
    for (int t = tid; t < TT; t += NTHR) {
        int uf = ((t % (fclk[t] + 1)) == 0) ? 1 : 0;
        int up = ((t % (pclk[t] + 1)) == 0) ? 1 : 0;
        int us = (sfreq[t] == 1) ? 1 : 0;
        flags[t] = (unsigned char)(uf | (up << 1) | (us << 2));
    }

    // ---- zero-init state + xs pad (pad lanes 24..31 stay zero forever) ----
    {
        float4 z = make_float4(0.f, 0.f, 0.f, 0.f);
        sw[w].hf[j] = z; sw[w].hp[j] = z;
        sw[w].hs0[j] = z; sw[w].hs1[j] = z; sw[w].hs2[j] = z;
        sw[w].xs[0][j] = z; sw[w].xs[1][j] = z;
        if (j < 8) { sw[w].xf[0][j] = z; sw[w].xf[1][j] = z;
                     sw[w].xp[0][j] = z; sw[w].xp[1][j] = z; }
    }
    __syncthreads();

    // ---- per-lane weight column j in registers (144 scalars) ----
    float wxf[DF], wxp[DF], whf[HH], whp[HH], wxs[HH], whs[HH];
#pragma unroll
    for (int k = 0; k < DF; k++) { wxf[k] = Wxf[k * HH + j]; wxp[k] = Wxp[k * HH + j]; }
#pragma unroll
    for (int i = 0; i < HH; i++) {
        whf[i] = Whf[i * HH + j]; whp[i] = Whp[i * HH + j];
        wxs[i] = Wxs[i * HH + j]; whs[i] = Whs[i * HH + j];
    }
    const float bf = bfv[j], bp = bpv[j], bs = bsv[j];

    const int b0 = (blockIdx.x * WPB + w) * 4;   // this warp's 4 batch rows

    // ---- staging addressing ----
    // xf/xp: lane l -> batch (l>>3), feature (l&7)   (32 scalars = 4 batch * 8)
    const float* pf = frnn  + (size_t)(b0 + (lane >> 3)) * DF + (lane & 7);
    const float* pp = phrnn + (size_t)(b0 + (lane >> 3)) * DF + (lane & 7);
    // xs: 96 scalars (4 batch * 24), 3 per lane
    const int fl0 = lane, fl1 = lane + 32, fl2 = lane + 64;
    const float* ps0 = syl + (size_t)(b0 + fl0 / 24) * DS + (fl0 % 24);
    const float* ps1 = syl + (size_t)(b0 + fl1 / 24) * DS + (fl1 % 24);
    const float* ps2 = syl + (size_t)(b0 + fl2 / 24) * DS + (fl2 % 24);

    float* xfd  = (float*)&sw[w].xf[0][lane & 7] + (lane >> 3);
    float* xpd  = (float*)&sw[w].xp[0][lane & 7] + (lane >> 3);
    float* xsd0 = (float*)&sw[w].xs[0][fl0 % 24] + (fl0 / 24);
    float* xsd1 = (float*)&sw[w].xs[0][fl1 % 24] + (fl1 / 24);
    float* xsd2 = (float*)&sw[w].xs[0][fl2 % 24] + (fl2 / 24);

    const size_t strFP = (size_t)BB * DF;   // per-t stride (floats)
    const size_t strS  = (size_t)BB * DS;

    // prefetch t = 0
    float vf = pf[0], vp = pp[0];
    float v0 = ps0[0], v1 = ps1[0], v2 = ps2[0];

    for (int t = 0; t < TT; t++) {
        const int par = t & 1;

        // stage x(t) from prefetch regs into ping-pong buffers
        xfd[par * 32]   = vf;  xpd[par * 32]   = vp;
        xsd0[par * 128] = v0;  xsd1[par * 128] = v1;  xsd2[par * 128] = v2;

        // prefetch x(t+1) — independent, hides DRAM latency behind compute
        const size_t tn = (t + 1 < TT) ? (size_t)(t + 1) : (size_t)(TT - 1);
        vf = pf[tn * strFP];  vp = pp[tn * strFP];
        v0 = ps0[tn * strS];  v1 = ps1[tn * strS];  v2 = ps2[tn * strS];

        const unsigned fl = flags[t];
        __syncwarp();                      // S1: staged x visible; x-WAR fence

        const bool uf = (fl & 1) != 0;
        const bool up = (fl & 2) != 0;
        const bool us = (fl & 4) != 0;

        float4 nf, np;
        if (uf | up) {
            if (uf) {
                u64 a = dup2(bf), b = dup2(bf);
                const ulonglong2* xv = (const ulonglong2*)sw[w].xf[par];
#pragma unroll
                for (int k = 0; k < DF; k++) {
                    ulonglong2 x = xv[k]; u64 wd = dup2(wxf[k]);
                    fma2(a, x.x, wd); fma2(b, x.y, wd);
                }
                const ulonglong2* hv = (const ulonglong2*)sw[w].hf;
#pragma unroll
                for (int i = 0; i < HH; i++) {
                    ulonglong2 h = hv[i]; u64 wd = dup2(whf[i]);
                    fma2(a, h.x, wd); fma2(b, h.y, wd);
                }
                float q0, q1, q2, q3; unpack2(a, q0, q1); unpack2(b, q2, q3);
                nf = make_float4(tanh_fast(q0), tanh_fast(q1), tanh_fast(q2), tanh_fast(q3));
            }
            if (up) {
                u64 a = dup2(bp), b = dup2(bp);
                const ulonglong2* xv = (const ulonglong2*)sw[w].xp[par];
#pragma unroll
                for (int k = 0; k < DF; k++) {
                    ulonglong2 x = xv[k]; u64 wd = dup2(wxp[k]);
                    fma2(a, x.x, wd); fma2(b, x.y, wd);
                }
                const ulonglong2* hv = (const ulonglong2*)sw[w].hp;
#pragma unroll
                for (int i = 0; i < HH; i++) {
                    ulonglong2 h = hv[i]; u64 wd = dup2(whp[i]);
                    fma2(a, h.x, wd); fma2(b, h.y, wd);
                }
                float q0, q1, q2, q3; unpack2(a, q0, q1); unpack2(b, q2, q3);
                np = make_float4(tanh_fast(q0), tanh_fast(q1), tanh_fast(q2), tanh_fast(q3));
            }
            __syncwarp();                  // S2: all lanes done reading old hf/hp
            if (uf) sw[w].hf[j] = nf;
            if (up) sw[w].hp[j] = np;
        }

        if (us) {
            __syncwarp();                  // S3: new hf/hp visible before syl reads
            const u64 bsd = dup2(bs);
            u64 s0a = bsd, s0b = bsd, s1a = bsd, s1b = bsd, s2a = bsd, s2b = bsd;
            const ulonglong2* hfv = (const ulonglong2*)sw[w].hf;
            const ulonglong2* hpv = (const ulonglong2*)sw[w].hp;
            const ulonglong2* xsv = (const ulonglong2*)sw[w].xs[par];
#pragma unroll
            for (int i = 0; i < HH; i++) {            // Wx_s shared across 3 rows
                u64 wd = dup2(wxs[i]);
                ulonglong2 A = hfv[i], B = hpv[i], C = xsv[i];
                fma2(s0a, A.x, wd); fma2(s0b, A.y, wd);
                fma2(s1a, B.x, wd); fma2(s1b, B.y, wd);
                fma2(s2a, C.x, wd); fma2(s2b, C.y, wd);
            }
            const ulonglong2* h0v = (const ulonglong2*)sw[w].hs0;
            const ulonglong2* h1v = (const ulonglong2*)sw[w].hs1;
            const ulonglong2* h2v = (const ulonglong2*)sw[w].hs2;
#pragma unroll
            for (int i = 0; i < HH; i++) {            // Wh_s shared across 3 rows
                u64 wd = dup2(whs[i]);
                ulonglong2 A = h0v[i], B = h1v[i], C = h2v[i];
                fma2(s0a, A.x, wd); fma2(s0b, A.y, wd);
                fma2(s1a, B.x, wd); fma2(s1b, B.y, wd);
                fma2(s2a, C.x, wd); fma2(s2b, C.y, wd);
            }
            float q0, q1, q2, q3;
            unpack2(s0a, q0, q1); unpack2(s0b, q2, q3);
            float4 n0 = make_float4(tanh_fast(q0), tanh_fast(q1), tanh_fast(q2), tanh_fast(q3));
            unpack2(s1a, q0, q1); unpack2(s1b, q2, q3);
            float4 n1 = make_float4(tanh_fast(q0), tanh_fast(q1), tanh_fast(q2), tanh_fast(q3));
            unpack2(s2a, q0, q1); unpack2(s2b, q2, q3);
            float4 n2 = make_float4(tanh_fast(q0), tanh_fast(q1), tanh_fast(q2), tanh_fast(q3));
            __syncwarp();                  // S4: all lanes done reading old hs
            sw[w].hs0[j] = n0; sw[w].hs1[j] = n1; sw[w].hs2[j] = n2;
        }
    }

    // ---- output: h_s final, shape [3, B, H]  (lane reads its own writes) ----
    {
        float4 v;
        v = sw[w].hs0[j];
        out[((size_t)0 * BB + b0 + 0) * HH + j] = v.x;
        out[((size_t)0 * BB + b0 + 1) * HH + j] = v.y;
        out[((size_t)0 * BB + b0 + 2) * HH + j] = v.z;
        out[((size_t)0 * BB + b0 + 3) * HH + j] = v.w;
        v = sw[w].hs1[j];
        out[((size_t)1 * BB + b0 + 0) * HH + j] = v.x;
        out[((size_t)1 * BB + b0 + 1) * HH + j] = v.y;
        out[((size_t)1 * BB + b0 + 2) * HH + j] = v.z;
        out[((size_t)1 * BB + b0 + 3) * HH + j] = v.w;
        v = sw[w].hs2[j];
        out[((size_t)2 * BB + b0 + 0) * HH + j] = v.x;
        out[((size_t)2 * BB + b0 + 1) * HH + j] = v.y;
        out[((size_t)2 * BB + b0 + 2) * HH + j] = v.z;
        out[((size_t)2 * BB + b0 + 3) * HH + j] = v.w;
    }
}

extern "C" void kernel_launch(void* const* d_in, const int* in_sizes, int n_in,
                              void* d_out, int out_size)
{
    (void)in_sizes; (void)n_in; (void)out_size;
    chive_kernel<<<NBLK, NTHR>>>(
        (const float*)d_in[0],  (const float*)d_in[1],  (const float*)d_in[2],
        (const float*)d_in[3],  (const float*)d_in[4],  (const float*)d_in[5],
        (const float*)d_in[6],  (const float*)d_in[7],  (const float*)d_in[8],
        (const float*)d_in[9],  (const float*)d_in[10], (const float*)d_in[11],
        (const int*)d_in[12],   (const int*)d_in[13],   (const int*)d_in[14],
        (float*)d_out);
}

// round 2
// speedup vs baseline: 1.2996x; 1.2996x over previous
#include <cuda_runtime.h>

#define TT   2048
#define BB   2048
#define HH   32
#define DF   8
#define DS   24
#define GPB  4                 // 4-batch groups per block
#define NW   (GPB * 3)         // 12 warps: (A,B,C) x 4 groups
#define NTHR (NW * 32)         // 384 threads
#define NBLK (BB / (GPB * 4))  // 128 blocks

typedef unsigned long long u64;

__device__ __forceinline__ u64 dup2(float w) {
    u64 d; asm("mov.b64 %0, {%1, %1};" : "=l"(d) : "f"(w)); return d;
}
__device__ __forceinline__ void unpack2(u64 v, float &a, float &b) {
    asm("mov.b64 {%0, %1}, %2;" : "=f"(a), "=f"(b) : "l"(v));
}
__device__ __forceinline__ void fma2(u64 &acc, u64 a, u64 b) {
    asm("fma.rn.f32x2 %0, %1, %2, %0;" : "+l"(acc) : "l"(a), "l"(b));
}
__device__ __forceinline__ float tanh_fast(float x) {
    float e = __expf(2.0f * x);
    return 1.0f - __fdividef(2.0f, e + 1.0f);
}

struct GroupSW {
    float4 hA[HH];                 // h_f  (warp A)
    float4 hB[HH];                 // h_p  (warp B)
    float4 s0[HH], s1[HH], s2[HH]; // h_s rows (A, B, C)
    float4 xA[2][DF], xB[2][DF];   // staged x_f / x_p, ping-pong
    float4 xC[2][HH];              // staged x_s (rows 24..31 stay zero = pad)
};

__global__ void __launch_bounds__(NTHR, 1) chive_kernel(
    const float* __restrict__ frnn, const float* __restrict__ phrnn, const float* __restrict__ syl,
    const float* __restrict__ Wxf, const float* __restrict__ Whf, const float* __restrict__ bfv,
    const float* __restrict__ Wxp, const float* __restrict__ Whp, const float* __restrict__ bpv,
    const float* __restrict__ Wxs, const float* __restrict__ Whs, const float* __restrict__ bsv,
    const int* __restrict__ fclk, const int* __restrict__ pclk, const int* __restrict__ sfreq,
    float* __restrict__ out)
{
    __shared__ GroupSW sw[GPB];
    __shared__ unsigned char flags[TT];

    const int tid  = threadIdx.x;
    const int wid  = tid >> 5;
    const int lane = tid & 31;
    const int grp  = wid / 3;
    const int role = wid % 3;      // 0 = f-cell+row0, 1 = p-cell+row1, 2 = row2
    const int j    = lane;

    // ---- zero all state + staging (pad rows of xC rely on this) ----
    for (int i = tid; i < (int)(sizeof(GroupSW) / 4) * GPB; i += NTHR)
        ((float*)sw)[i] = 0.0f;

    // ---- warp-uniform update masks, depend only on t ----
    for (int t = tid; t < TT; t += NTHR) {
        int uf = ((t % (fclk[t] + 1)) == 0) ? 1 : 0;
        int up = ((t % (pclk[t] + 1)) == 0) ? 1 : 0;
        int us = (sfreq[t] == 1) ? 1 : 0;
        flags[t] = (unsigned char)(uf | (up << 1) | (us << 2));
    }
    __syncthreads();

    GroupSW& G = sw[grp];
    const int b0 = (blockIdx.x * GPB + grp) * 4;   // this group's 4 batch rows

    // ---- syl weight column j (all roles) ----
    float wsx[HH], wsh[HH];
#pragma unroll
    for (int i = 0; i < HH; i++) { wsx[i] = Wxs[i * HH + j]; wsh[i] = Whs[i * HH + j]; }
    const float bs_ = bsv[j];

    float4* srow = (role == 0) ? G.s0 : (role == 1) ? G.s1 : G.s2;

    if (role < 2) {
        // ================= warp A / B: clockwork cell + its syl row =================
        const float* xsrc = (role == 0) ? frnn : phrnn;
        const float* Wx   = (role == 0) ? Wxf  : Wxp;
        const float* Wh   = (role == 0) ? Whf  : Whp;
        const float* bv   = (role == 0) ? bfv  : bpv;
        float4* hst       = (role == 0) ? G.hA : G.hB;
        float4 (*xbuf)[DF] = (role == 0) ? G.xA : G.xB;
        const unsigned bit = 1u << role;

        float wx[DF], wh[HH];
#pragma unroll
        for (int k = 0; k < DF; k++) wx[k] = Wx[k * HH + j];
#pragma unroll
        for (int i = 0; i < HH; i++) wh[i] = Wh[i * HH + j];
        const float bc = bv[j];

        // staging: lane -> batch (lane>>3), feature (lane&7)
        const float* px = xsrc + (size_t)(b0 + (lane >> 3)) * DF + (lane & 7);
        float* xd = (float*)xbuf + (lane & 7) * 4 + (lane >> 3);
        const size_t str = (size_t)BB * DF;

        float v = px[0];                      // prefetch t=0
        for (int t = 0; t < TT; t++) {
            const int par = t & 1;
            xd[par * 32] = v;
            const size_t tn = (t + 1 < TT) ? (size_t)(t + 1) : (size_t)(TT - 1);
            v = px[tn * str];                 // prefetch next step
            const unsigned fl = flags[t];
            __syncwarp();                     // staged x visible; prior writes ordered

            if (fl & bit) {                   // clockwork cell update
                u64 a = dup2(bc), b = dup2(bc);
                const ulonglong2* xv = (const ulonglong2*)xbuf[par];
#pragma unroll
                for (int k = 0; k < DF; k++) {
                    ulonglong2 x = xv[k]; u64 wd = dup2(wx[k]);
                    fma2(a, x.x, wd); fma2(b, x.y, wd);
                }
                const ulonglong2* hv = (const ulonglong2*)hst;
#pragma unroll
                for (int i = 0; i < HH; i++) {
                    ulonglong2 h = hv[i]; u64 wd = dup2(wh[i]);
                    fma2(a, h.x, wd); fma2(b, h.y, wd);
                }
                float q0, q1, q2, q3; unpack2(a, q0, q1); unpack2(b, q2, q3);
                float4 nf = make_float4(tanh_fast(q0), tanh_fast(q1),
                                        tanh_fast(q2), tanh_fast(q3));
                __syncwarp();                 // all lanes done reading old h
                hst[j] = nf;
            }
            if (fl & 4) {                     // syl row update (uses fresh h)
                __syncwarp();                 // h writes visible to all lanes
                u64 a = dup2(bs_), b = dup2(bs_);
                const ulonglong2* hv = (const ulonglong2*)hst;
#pragma unroll
                for (int i = 0; i < HH; i++) {
                    ulonglong2 h = hv[i]; u64 wd = dup2(wsx[i]);
                    fma2(a, h.x, wd); fma2(b, h.y, wd);
                }
                const ulonglong2* rv = (const ulonglong2*)srow;
#pragma unroll
                for (int i = 0; i < HH; i++) {
                    ulonglong2 h = rv[i]; u64 wd = dup2(wsh[i]);
                    fma2(a, h.x, wd); fma2(b, h.y, wd);
                }
                float q0, q1, q2, q3; unpack2(a, q0, q1); unpack2(b, q2, q3);
                float4 n = make_float4(tanh_fast(q0), tanh_fast(q1),
                                       tanh_fast(q2), tanh_fast(q3));
                __syncwarp();                 // all lanes done reading old srow
                srow[j] = n;
            }
        }
    } else {
        // ================= warp C: x_s-driven syl row (fully independent) =========
        const int fl0 = lane, fl1 = lane + 32, fl2 = lane + 64;   // 96 scalars
        const float* p0 = syl + (size_t)(b0 + fl0 / 24) * DS + (fl0 % 24);
        const float* p1 = syl + (size_t)(b0 + fl1 / 24) * DS + (fl1 % 24);
        const float* p2 = syl + (size_t)(b0 + fl2 / 24) * DS + (fl2 % 24);
        float* d0 = (float*)G.xC + (fl0 % 24) * 4 + (fl0 / 24);
        float* d1 = (float*)G.xC + (fl1 % 24) * 4 + (fl1 / 24);
        float* d2 = (float*)G.xC + (fl2 % 24) * 4 + (fl2 / 24);
        const size_t str = (size_t)BB * DS;

        float v0 = p0[0], v1 = p1[0], v2 = p2[0];
        for (int t = 0; t < TT; t++) {
            const int par = t & 1;
            d0[par * 128] = v0; d1[par * 128] = v1; d2[par * 128] = v2;
            const size_t tn = (t + 1 < TT) ? (size_t)(t + 1) : (size_t)(TT - 1);
            v0 = p0[tn * str]; v1 = p1[tn * str]; v2 = p2[tn * str];
            const unsigned fl = flags[t];
            __syncwarp();

            if (fl & 4) {
                u64 a = dup2(bs_), b = dup2(bs_);
                const ulonglong2* xv = (const ulonglong2*)G.xC[par];
#pragma unroll
                for (int i = 0; i < HH; i++) {     // rows 24..31 are zero pad
                    ulonglong2 x = xv[i]; u64 wd = dup2(wsx[i]);
                    fma2(a, x.x, wd); fma2(b, x.y, wd);
                }
                const ulonglong2* rv = (const ulonglong2*)srow;
#pragma unroll
                for (int i = 0; i < HH; i++) {
                    ulonglong2 h = rv[i]; u64 wd = dup2(wsh[i]);
                    fma2(a, h.x, wd); fma2(b, h.y, wd);
                }
                float q0, q1, q2, q3; unpack2(a, q0, q1); unpack2(b, q2, q3);
                float4 n = make_float4(tanh_fast(q0), tanh_fast(q1),
                                       tanh_fast(q2), tanh_fast(q3));
                __syncwarp();
                srow[j] = n;
            }
        }
    }

    // ---- output: each warp writes its own h_s row; lane j reads its own writes ----
    {
        float4 vv = srow[j];
        out[((size_t)role * BB + b0 + 0) * HH + j] = vv.x;
        out[((size_t)role * BB + b0 + 1) * HH + j] = vv.y;
        out[((size_t)role * BB + b0 + 2) * HH + j] = vv.z;
        out[((size_t)role * BB + b0 + 3) * HH + j] = vv.w;
    }
}

extern "C" void kernel_launch(void* const* d_in, const int* in_sizes, int n_in,
                              void* d_out, int out_size)
{
    (void)in_sizes; (void)n_in; (void)out_size;
    chive_kernel<<<NBLK, NTHR>>>(
        (const float*)d_in[0],  (const float*)d_in[1],  (const float*)d_in[2],
        (const float*)d_in[3],  (const float*)d_in[4],  (const float*)d_in[5],
        (const float*)d_in[6],  (const float*)d_in[7],  (const float*)d_in[8],
        (const float*)d_in[9],  (const float*)d_in[10], (const float*)d_in[11],
        (const int*)d_in[12],   (const int*)d_in[13],   (const int*)d_in[14],
        (float*)d_out);
}